// round 2
// baseline (speedup 1.0000x reference)
#include <cuda_runtime.h>
#include <cuda_bf16.h>
#include <math.h>

// Problem constants
#define S 2048
#define D_MODEL 2560
#define NUM_HEADS 32
#define NUM_KV_HEADS 8
#define HEAD_DIM 128
#define QDIM (NUM_HEADS * HEAD_DIM)     // 4096
#define KVDIM (NUM_KV_HEADS * HEAD_DIM) // 1024
#define EPS 1e-6f
#define ROPE_THETA 5000000.0f

// Scratch (no allocs allowed -> __device__ globals)
__device__ float g_Q[S * QDIM];
__device__ float g_K[S * KVDIM];
__device__ float g_V[S * KVDIM];
__device__ float g_O[S * QDIM];

// ----------------------------------------------------------------------------
// Tiled NT GEMM: C[M,N] = A[M,K] @ B[N,K]^T   (A row-major, B row-major [N,K])
// BM=BN=64, BK=16, 256 threads, 4x4 per thread. All dims divisible.
// ----------------------------------------------------------------------------
#define BM 64
#define BN 64
#define BK 16

__global__ void gemm_nt(const float* __restrict__ A, const float* __restrict__ B,
                        float* __restrict__ C, int M, int N, int K) {
    __shared__ float As[BK][BM];
    __shared__ float Bs[BK][BN];

    int tid = threadIdx.x;          // 0..255
    int tx = tid & 15;              // 0..15
    int ty = tid >> 4;              // 0..15
    int row0 = blockIdx.y * BM + ty * 4;
    int col0 = blockIdx.x * BN + tx * 4;

    float acc[4][4] = {};

    for (int k0 = 0; k0 < K; k0 += BK) {
        // Load A tile (64x16) and B tile (64x16), 4 elems per thread, coalesced in K.
#pragma unroll
        for (int i = 0; i < 4; i++) {
            int idx = tid + i * 256;     // 0..1023
            int m = idx >> 4;            // 0..63
            int kk = idx & 15;
            As[kk][m] = A[(size_t)(blockIdx.y * BM + m) * K + k0 + kk];
            Bs[kk][m] = B[(size_t)(blockIdx.x * BN + m) * K + k0 + kk];
        }
        __syncthreads();
#pragma unroll
        for (int kk = 0; kk < BK; kk++) {
            float a[4], b[4];
#pragma unroll
            for (int i = 0; i < 4; i++) a[i] = As[kk][ty * 4 + i];
#pragma unroll
            for (int j = 0; j < 4; j++) b[j] = Bs[kk][tx * 4 + j];
#pragma unroll
            for (int i = 0; i < 4; i++)
#pragma unroll
                for (int j = 0; j < 4; j++)
                    acc[i][j] = fmaf(a[i], b[j], acc[i][j]);
        }
        __syncthreads();
    }
#pragma unroll
    for (int i = 0; i < 4; i++)
#pragma unroll
        for (int j = 0; j < 4; j++)
            C[(size_t)(row0 + i) * N + col0 + j] = acc[i][j];
}

// ----------------------------------------------------------------------------
// RMSNorm + RoPE for one (pos, head) row of 128 dims.
// mode 0: Q in g_Q (in-place).  mode 1: K from g_K -> cache_k region of d_out.
// ----------------------------------------------------------------------------
__global__ void norm_rope_kernel(const float* __restrict__ src, float* __restrict__ dst,
                                 const float* __restrict__ w, int nheads, int dst_is_cache) {
    int s = blockIdx.x;      // position
    int h = blockIdx.y;      // head
    int d = threadIdx.x;     // 0..127

    __shared__ float sh[HEAD_DIM];
    __shared__ float red[4];

    float x = src[(size_t)s * (nheads * HEAD_DIM) + h * HEAD_DIM + d];

    // sum of squares across 128 lanes (4 warps)
    float sq = x * x;
#pragma unroll
    for (int off = 16; off > 0; off >>= 1)
        sq += __shfl_down_sync(0xffffffff, sq, off);
    if ((d & 31) == 0) red[d >> 5] = sq;
    __syncthreads();
    float var = (red[0] + red[1] + red[2] + red[3]) * (1.0f / HEAD_DIM);
    float r = rsqrtf(var + EPS);
    float xn = x * r * w[d];
    sh[d] = xn;
    __syncthreads();

    // RoPE
    int f = d & 63;
    float inv_freq = powf(ROPE_THETA, -((float)f) / 64.0f);
    float ang = (float)s * inv_freq;
    float c = cosf(ang), sn = sinf(ang);
    float out;
    if (d < 64) out = xn * c - sh[d + 64] * sn;
    else        out = xn * c + sh[d - 64] * sn;

    if (dst_is_cache) {
        // cache layout [g, s, d]
        dst[((size_t)h * S + s) * HEAD_DIM + d] = out;
    } else {
        dst[(size_t)s * (nheads * HEAD_DIM) + h * HEAD_DIM + d] = out;
    }
}

// V: transpose [s, g, d] -> cache [g, s, d]
__global__ void v_to_cache_kernel(const float* __restrict__ src, float* __restrict__ dst) {
    int s = blockIdx.x;
    int g = blockIdx.y;
    int d = threadIdx.x;
    dst[((size_t)g * S + s) * HEAD_DIM + d] = src[(size_t)s * KVDIM + g * HEAD_DIM + d];
}

// ----------------------------------------------------------------------------
// Flash attention: one block per (qTile of 64, head). 256 threads.
// Online softmax over key tiles of 64. K/V read from the cache regions in d_out.
// Dynamic smem: Qs[64*128] + KVs[64*128] + Ss[64*64] = 80 KB.
// ----------------------------------------------------------------------------
#define QT 64
#define KT 64

__global__ void flash_kernel(const float* __restrict__ cacheK,
                             const float* __restrict__ cacheV) {
    extern __shared__ float smem[];
    float* Qs  = smem;                    // QT x 128
    float* KVs = smem + QT * HEAD_DIM;    // KT x 128
    float* Ss  = smem + 2 * QT * HEAD_DIM; // QT x KT

    int qTile = blockIdx.x;
    int h = blockIdx.y;
    int g = h >> 2;                        // kv head
    int tid = threadIdx.x;                 // 0..255
    int qBase = qTile * QT;

    // Load Q tile
#pragma unroll
    for (int j = 0; j < (QT * HEAD_DIM) / 256; j++) {
        int idx = tid + j * 256;
        int i = idx >> 7;       // row
        int d = idx & 127;
        Qs[idx] = g_Q[(size_t)(qBase + i) * QDIM + h * HEAD_DIM + d];
    }

    int row = tid >> 2;          // 0..63  (query row in tile)
    int quarter = tid & 3;       // which 32-col chunk of O / 16-col chunk of S
    int c0 = quarter * 32;
    int j0 = quarter * 16;

    float acc[32];
#pragma unroll
    for (int c = 0; c < 32; c++) acc[c] = 0.0f;
    float m = -INFINITY, l = 0.0f;

    const float scale = 0.08838834764831845f; // 1/sqrt(128)

    __syncthreads();

    for (int kt = 0; kt <= qTile; kt++) {
        int kBase = kt * KT;
        // load K tile
#pragma unroll
        for (int j = 0; j < (KT * HEAD_DIM) / 256; j++) {
            int idx = tid + j * 256;
            int i = idx >> 7;
            int d = idx & 127;
            KVs[idx] = cacheK[((size_t)g * S + kBase + i) * HEAD_DIM + d];
        }
        __syncthreads();

        // scores: thread computes S[row][j0..j0+16)
        {
            float sacc[16];
#pragma unroll
            for (int j = 0; j < 16; j++) sacc[j] = 0.0f;
            const float* qrow = &Qs[row * HEAD_DIM];
#pragma unroll 4
            for (int d = 0; d < HEAD_DIM; d++) {
                float qv = qrow[d];
#pragma unroll
                for (int j = 0; j < 16; j++)
                    sacc[j] = fmaf(qv, KVs[(j0 + j) * HEAD_DIM + d], sacc[j]);
            }
            int qi = qBase + row;
#pragma unroll
            for (int j = 0; j < 16; j++) {
                int kj = kBase + j0 + j;
                Ss[row * KT + j0 + j] = (kj <= qi) ? sacc[j] * scale : -INFINITY;
            }
        }
        __syncthreads();

        // online softmax stats (each of the 4 threads per row computes same m,l)
        float rowmax = -INFINITY;
#pragma unroll 8
        for (int j = 0; j < KT; j++) rowmax = fmaxf(rowmax, Ss[row * KT + j]);
        float m_new = fmaxf(m, rowmax);
        float corr = expf(m - m_new);
        float rsum = 0.0f;
#pragma unroll 8
        for (int j = 0; j < KT; j++) rsum += expf(Ss[row * KT + j] - m_new);
        l = l * corr + rsum;
#pragma unroll
        for (int c = 0; c < 32; c++) acc[c] *= corr;
        __syncthreads();

        // write P (exp) back into Ss — each thread owns its 16-col slice
#pragma unroll
        for (int j = 0; j < 16; j++) {
            float v = Ss[row * KT + j0 + j];
            Ss[row * KT + j0 + j] = expf(v - m_new);
        }
        m = m_new;
        __syncthreads();

        // load V tile into KVs (K no longer needed)
#pragma unroll
        for (int j = 0; j < (KT * HEAD_DIM) / 256; j++) {
            int idx = tid + j * 256;
            int i = idx >> 7;
            int d = idx & 127;
            KVs[idx] = cacheV[((size_t)g * S + kBase + i) * HEAD_DIM + d];
        }
        __syncthreads();

        // O += P @ V  (thread: row, cols c0..c0+32)
#pragma unroll 4
        for (int j = 0; j < KT; j++) {
            float p = Ss[row * KT + j];
#pragma unroll
            for (int c = 0; c < 32; c++)
                acc[c] = fmaf(p, KVs[j * HEAD_DIM + c0 + c], acc[c]);
        }
        __syncthreads();
    }

    float rinv = 1.0f / l;
#pragma unroll
    for (int c = 0; c < 32; c++)
        g_O[(size_t)(qBase + row) * QDIM + h * HEAD_DIM + c0 + c] = acc[c] * rinv;
}

// ----------------------------------------------------------------------------
extern "C" void kernel_launch(void* const* d_in, const int* in_sizes, int n_in,
                              void* d_out, int out_size) {
    const float* x  = (const float*)d_in[0];
    const float* Wq = (const float*)d_in[1];
    const float* Wk = (const float*)d_in[2];
    const float* Wv = (const float*)d_in[3];
    const float* Wo = (const float*)d_in[4];
    const float* qw = (const float*)d_in[5];
    const float* kw = (const float*)d_in[6];

    float* out     = (float*)d_out;                            // [S, D_MODEL]
    float* cacheK  = out + (size_t)S * D_MODEL;                // [G, S, 128]
    float* cacheV  = cacheK + (size_t)NUM_KV_HEADS * S * HEAD_DIM;

    float* dQ; cudaGetSymbolAddress((void**)&dQ, g_Q);
    float* dK; cudaGetSymbolAddress((void**)&dK, g_K);
    float* dV; cudaGetSymbolAddress((void**)&dV, g_V);
    float* dO; cudaGetSymbolAddress((void**)&dO, g_O);

    // 1) QKV projections
    {
        dim3 blk(256);
        gemm_nt<<<dim3(QDIM / BN, S / BM), blk>>>(x, Wq, dQ, S, QDIM, D_MODEL);
        gemm_nt<<<dim3(KVDIM / BN, S / BM), blk>>>(x, Wk, dK, S, KVDIM, D_MODEL);
        gemm_nt<<<dim3(KVDIM / BN, S / BM), blk>>>(x, Wv, dV, S, KVDIM, D_MODEL);
    }

    // 2) RMSNorm + RoPE (Q in-place; K -> cache), V -> cache
    norm_rope_kernel<<<dim3(S, NUM_HEADS), HEAD_DIM>>>(dQ, dQ, qw, NUM_HEADS, 0);
    norm_rope_kernel<<<dim3(S, NUM_KV_HEADS), HEAD_DIM>>>(dK, cacheK, kw, NUM_KV_HEADS, 1);
    v_to_cache_kernel<<<dim3(S, NUM_KV_HEADS), HEAD_DIM>>>(dV, cacheV);

    // 3) Flash attention
    {
        size_t smem_bytes = (2 * QT * HEAD_DIM + QT * KT) * sizeof(float); // 80 KB
        cudaFuncSetAttribute(flash_kernel, cudaFuncAttributeMaxDynamicSharedMemorySize,
                             (int)smem_bytes);
        flash_kernel<<<dim3(S / QT, NUM_HEADS), 256, smem_bytes>>>(cacheK, cacheV);
    }

    // 4) Output projection
    gemm_nt<<<dim3(D_MODEL / BN, S / BM), 256>>>(dO, Wo, out, S, D_MODEL, QDIM);
}

// round 5
// speedup vs baseline: 9.6582x; 9.6582x over previous
#include <cuda_runtime.h>
#include <cuda_bf16.h>
#include <math.h>

// Problem constants
#define S 2048
#define D_MODEL 2560
#define NUM_HEADS 32
#define NUM_KV_HEADS 8
#define HEAD_DIM 128
#define QDIM (NUM_HEADS * HEAD_DIM)     // 4096
#define KVDIM (NUM_KV_HEADS * HEAD_DIM) // 1024
#define EPS 1e-6f
#define ROPE_THETA 5000000.0f

// Scratch (no allocs allowed -> __device__ globals)
__device__ float g_Q[S * QDIM];
__device__ float g_K[S * KVDIM];
__device__ float g_V[S * KVDIM];
__device__ float g_O[S * QDIM];

// ----------------------------------------------------------------------------
// helpers
// ----------------------------------------------------------------------------
__device__ __forceinline__ float tf32r(float x) {
    unsigned u;
    asm("cvt.rna.tf32.f32 %0, %1;" : "=r"(u) : "f"(x));
    return __uint_as_float(u);
}

// D += A * B  (m16n8k8 tf32)
__device__ __forceinline__ void mma_tf32(float* d, const unsigned* a, const unsigned* b) {
    asm volatile(
        "mma.sync.aligned.m16n8k8.row.col.f32.tf32.tf32.f32 "
        "{%0,%1,%2,%3}, {%4,%5,%6,%7}, {%8,%9}, {%0,%1,%2,%3};"
        : "+f"(d[0]), "+f"(d[1]), "+f"(d[2]), "+f"(d[3])
        : "r"(a[0]), "r"(a[1]), "r"(a[2]), "r"(a[3]), "r"(b[0]), "r"(b[1]));
}

// ----------------------------------------------------------------------------
// tf32 NT GEMM: C[M,N] = A[M,K] @ B[N,K]^T
// BM=128 BN=64 BK=32, 256 threads (8 warps, 4x2), warp tile 32x32.
// smem strides BK+4=36 (== 4 mod 32) -> conflict-free fragment loads.
// ----------------------------------------------------------------------------
#define GBM 128
#define GBN 64
#define GBK 32
#define GSTRIDE (GBK + 4)

__global__ __launch_bounds__(256) void gemm_tf32(const float* __restrict__ A,
                                                 const float* __restrict__ B,
                                                 float* __restrict__ C,
                                                 int M, int N, int K) {
    __shared__ float As[GBM * GSTRIDE];
    __shared__ float Bs[GBN * GSTRIDE];

    const int tid = threadIdx.x;
    const int warp = tid >> 5;
    const int lane = tid & 31;
    const int wm = warp >> 1;       // 0..3
    const int wn = warp & 1;        // 0..1
    const int r = lane >> 2;        // 0..7
    const int cc = lane & 3;        // 0..3

    const int bm0 = blockIdx.y * GBM;
    const int bn0 = blockIdx.x * GBN;

    float4 ar[4], br[2];

    // stage 0 load
    {
        int k0 = 0;
#pragma unroll
        for (int i = 0; i < 4; i++) {
            int idx = tid + i * 256;
            int row = idx >> 3, c4 = idx & 7;
            ar[i] = *(const float4*)&A[(size_t)(bm0 + row) * K + k0 + c4 * 4];
        }
#pragma unroll
        for (int i = 0; i < 2; i++) {
            int idx = tid + i * 256;
            int row = idx >> 3, c4 = idx & 7;
            br[i] = *(const float4*)&B[(size_t)(bn0 + row) * K + k0 + c4 * 4];
        }
    }
    // store stage 0
#pragma unroll
    for (int i = 0; i < 4; i++) {
        int idx = tid + i * 256;
        int row = idx >> 3, c4 = idx & 7;
        float4 v = ar[i];
        v.x = tf32r(v.x); v.y = tf32r(v.y); v.z = tf32r(v.z); v.w = tf32r(v.w);
        *(float4*)&As[row * GSTRIDE + c4 * 4] = v;
    }
#pragma unroll
    for (int i = 0; i < 2; i++) {
        int idx = tid + i * 256;
        int row = idx >> 3, c4 = idx & 7;
        float4 v = br[i];
        v.x = tf32r(v.x); v.y = tf32r(v.y); v.z = tf32r(v.z); v.w = tf32r(v.w);
        *(float4*)&Bs[row * GSTRIDE + c4 * 4] = v;
    }
    __syncthreads();

    float acc[2][4][4];
#pragma unroll
    for (int mt = 0; mt < 2; mt++)
#pragma unroll
        for (int nt = 0; nt < 4; nt++)
#pragma unroll
            for (int i = 0; i < 4; i++) acc[mt][nt][i] = 0.0f;

    const int nk = K / GBK;
    for (int kt = 0; kt < nk; kt++) {
        // prefetch next tile into registers
        if (kt + 1 < nk) {
            int k0 = (kt + 1) * GBK;
#pragma unroll
            for (int i = 0; i < 4; i++) {
                int idx = tid + i * 256;
                int row = idx >> 3, c4 = idx & 7;
                ar[i] = *(const float4*)&A[(size_t)(bm0 + row) * K + k0 + c4 * 4];
            }
#pragma unroll
            for (int i = 0; i < 2; i++) {
                int idx = tid + i * 256;
                int row = idx >> 3, c4 = idx & 7;
                br[i] = *(const float4*)&B[(size_t)(bn0 + row) * K + k0 + c4 * 4];
            }
        }
        // compute current tile
#pragma unroll
        for (int ks = 0; ks < 4; ks++) {
            unsigned af[2][4];
#pragma unroll
            for (int mt = 0; mt < 2; mt++) {
                int m0 = wm * 32 + mt * 16;
                af[mt][0] = __float_as_uint(As[(m0 + r) * GSTRIDE + ks * 8 + cc]);
                af[mt][1] = __float_as_uint(As[(m0 + r + 8) * GSTRIDE + ks * 8 + cc]);
                af[mt][2] = __float_as_uint(As[(m0 + r) * GSTRIDE + ks * 8 + cc + 4]);
                af[mt][3] = __float_as_uint(As[(m0 + r + 8) * GSTRIDE + ks * 8 + cc + 4]);
            }
            unsigned bf[4][2];
#pragma unroll
            for (int nt = 0; nt < 4; nt++) {
                int n0 = wn * 32 + nt * 8 + r;
                bf[nt][0] = __float_as_uint(Bs[n0 * GSTRIDE + ks * 8 + cc]);
                bf[nt][1] = __float_as_uint(Bs[n0 * GSTRIDE + ks * 8 + cc + 4]);
            }
#pragma unroll
            for (int mt = 0; mt < 2; mt++)
#pragma unroll
                for (int nt = 0; nt < 4; nt++)
                    mma_tf32(acc[mt][nt], af[mt], bf[nt]);
        }
        __syncthreads();
        if (kt + 1 < nk) {
#pragma unroll
            for (int i = 0; i < 4; i++) {
                int idx = tid + i * 256;
                int row = idx >> 3, c4 = idx & 7;
                float4 v = ar[i];
                v.x = tf32r(v.x); v.y = tf32r(v.y); v.z = tf32r(v.z); v.w = tf32r(v.w);
                *(float4*)&As[row * GSTRIDE + c4 * 4] = v;
            }
#pragma unroll
            for (int i = 0; i < 2; i++) {
                int idx = tid + i * 256;
                int row = idx >> 3, c4 = idx & 7;
                float4 v = br[i];
                v.x = tf32r(v.x); v.y = tf32r(v.y); v.z = tf32r(v.z); v.w = tf32r(v.w);
                *(float4*)&Bs[row * GSTRIDE + c4 * 4] = v;
            }
            __syncthreads();
        }
    }

    // epilogue
#pragma unroll
    for (int mt = 0; mt < 2; mt++) {
#pragma unroll
        for (int nt = 0; nt < 4; nt++) {
            int row = bm0 + wm * 32 + mt * 16 + r;
            int col = bn0 + wn * 32 + nt * 8 + 2 * cc;
            float2 v0 = make_float2(acc[mt][nt][0], acc[mt][nt][1]);
            float2 v1 = make_float2(acc[mt][nt][2], acc[mt][nt][3]);
            *(float2*)&C[(size_t)row * N + col] = v0;
            *(float2*)&C[(size_t)(row + 8) * N + col] = v1;
        }
    }
}

// ----------------------------------------------------------------------------
// RMSNorm + RoPE
// ----------------------------------------------------------------------------
__global__ void norm_rope_kernel(const float* __restrict__ src, float* __restrict__ dst,
                                 const float* __restrict__ w, int nheads, int dst_is_cache) {
    int s = blockIdx.x;
    int h = blockIdx.y;
    int d = threadIdx.x;

    __shared__ float sh[HEAD_DIM];
    __shared__ float red[4];

    float x = src[(size_t)s * (nheads * HEAD_DIM) + h * HEAD_DIM + d];

    float sq = x * x;
#pragma unroll
    for (int off = 16; off > 0; off >>= 1)
        sq += __shfl_down_sync(0xffffffff, sq, off);
    if ((d & 31) == 0) red[d >> 5] = sq;
    __syncthreads();
    float var = (red[0] + red[1] + red[2] + red[3]) * (1.0f / HEAD_DIM);
    float r = rsqrtf(var + EPS);
    float xn = x * r * w[d];
    sh[d] = xn;
    __syncthreads();

    int f = d & 63;
    float inv_freq = powf(ROPE_THETA, -((float)f) / 64.0f);
    float ang = (float)s * inv_freq;
    float c = cosf(ang), sn = sinf(ang);
    float out;
    if (d < 64) out = xn * c - sh[d + 64] * sn;
    else        out = xn * c + sh[d - 64] * sn;

    if (dst_is_cache) {
        dst[((size_t)h * S + s) * HEAD_DIM + d] = out;
    } else {
        dst[(size_t)s * (nheads * HEAD_DIM) + h * HEAD_DIM + d] = out;
    }
}

__global__ void v_to_cache_kernel(const float* __restrict__ src, float* __restrict__ dst) {
    int s = blockIdx.x;
    int g = blockIdx.y;
    int d = threadIdx.x;
    dst[((size_t)g * S + s) * HEAD_DIM + d] = src[(size_t)s * KVDIM + g * HEAD_DIM + d];
}

// ----------------------------------------------------------------------------
// Flash attention with tf32 mma. Block: 128 threads (4 warps, 2x2),
// one (64-query tile, head) per block. Online softmax in smem.
//
// smem layout (floats):
//   Qs   [64][132]   @ 0       (8448)
//   KVs  K:[64][132] / V^T:[128][68]  @ 8448 (8704)
//   Ps   [64][68]    @ 17152   (4352)   raw S then P
//   mS[64] lS[64] corrS[64] @ 21504
// total 21696 floats = 86784 B
// ----------------------------------------------------------------------------
#define FQT 64
#define FKT 64
#define QS_OFF 0
#define KV_OFF 8448
#define PS_OFF 17152
#define MS_OFF 21504
#define LS_OFF 21568
#define CS_OFF 21632
#define FSMEM_FLOATS 21696

__global__ __launch_bounds__(128) void flash_tf32(const float* __restrict__ cacheK,
                                                  const float* __restrict__ cacheV) {
    extern __shared__ float fsm[];
    float* Qs = fsm + QS_OFF;     // stride 132
    float* KVs = fsm + KV_OFF;    // K stride 132 / V^T stride 68
    float* Ps = fsm + PS_OFF;     // stride 68
    float* mS = fsm + MS_OFF;
    float* lS = fsm + LS_OFF;
    float* corrS = fsm + CS_OFF;

    const int qTile = blockIdx.x;
    const int h = blockIdx.y;
    const int g = h >> 2;
    const int tid = threadIdx.x;
    const int warp = tid >> 5;
    const int lane = tid & 31;
    const int wm = warp >> 1;    // 0..1
    const int wn = warp & 1;     // 0..1
    const int r = lane >> 2;     // 0..7
    const int cc = lane & 3;     // 0..3
    const int qBase = qTile * FQT;
    const float scale = 0.08838834764831845f;

    // init stats
    if (tid < 64) { mS[tid] = -INFINITY; lS[tid] = 0.0f; }

    // load Q tile (64 x 128), cvt to tf32
#pragma unroll
    for (int i = 0; i < 16; i++) {
        int idx = tid + i * 128;
        int row = idx >> 5, c4 = idx & 31;
        float4 v = *(const float4*)&g_Q[(size_t)(qBase + row) * QDIM + h * HEAD_DIM + c4 * 4];
        v.x = tf32r(v.x); v.y = tf32r(v.y); v.z = tf32r(v.z); v.w = tf32r(v.w);
        *(float4*)&Qs[row * 132 + c4 * 4] = v;
    }

    // O accumulators: warp covers rows wm*32..+32, cols wn*64..+64
    float oacc[2][8][4];
#pragma unroll
    for (int mt = 0; mt < 2; mt++)
#pragma unroll
        for (int nt = 0; nt < 8; nt++)
#pragma unroll
            for (int i = 0; i < 4; i++) oacc[mt][nt][i] = 0.0f;

    __syncthreads();

    for (int kt = 0; kt <= qTile; kt++) {
        const int kBase = kt * FKT;

        // load K tile (64 x 128) into KVs stride 132
#pragma unroll
        for (int i = 0; i < 16; i++) {
            int idx = tid + i * 128;
            int row = idx >> 5, c4 = idx & 31;
            float4 v = *(const float4*)&cacheK[((size_t)g * S + kBase + row) * HEAD_DIM + c4 * 4];
            v.x = tf32r(v.x); v.y = tf32r(v.y); v.z = tf32r(v.z); v.w = tf32r(v.w);
            *(float4*)&KVs[row * 132 + c4 * 4] = v;
        }
        __syncthreads();

        // S = Q K^T  (64x64x128), warp tile 32x32
        float sacc[2][4][4];
#pragma unroll
        for (int mt = 0; mt < 2; mt++)
#pragma unroll
            for (int nt = 0; nt < 4; nt++)
#pragma unroll
                for (int i = 0; i < 4; i++) sacc[mt][nt][i] = 0.0f;

#pragma unroll
        for (int ks = 0; ks < 16; ks++) {
            unsigned af[2][4];
#pragma unroll
            for (int mt = 0; mt < 2; mt++) {
                int m0 = wm * 32 + mt * 16;
                af[mt][0] = __float_as_uint(Qs[(m0 + r) * 132 + ks * 8 + cc]);
                af[mt][1] = __float_as_uint(Qs[(m0 + r + 8) * 132 + ks * 8 + cc]);
                af[mt][2] = __float_as_uint(Qs[(m0 + r) * 132 + ks * 8 + cc + 4]);
                af[mt][3] = __float_as_uint(Qs[(m0 + r + 8) * 132 + ks * 8 + cc + 4]);
            }
            unsigned bf[4][2];
#pragma unroll
            for (int nt = 0; nt < 4; nt++) {
                int n0 = wn * 32 + nt * 8 + r;
                bf[nt][0] = __float_as_uint(KVs[n0 * 132 + ks * 8 + cc]);
                bf[nt][1] = __float_as_uint(KVs[n0 * 132 + ks * 8 + cc + 4]);
            }
#pragma unroll
            for (int mt = 0; mt < 2; mt++)
#pragma unroll
                for (int nt = 0; nt < 4; nt++)
                    mma_tf32(sacc[mt][nt], af[mt], bf[nt]);
        }

        // write masked, scaled S to Ps
#pragma unroll
        for (int mt = 0; mt < 2; mt++) {
#pragma unroll
            for (int nt = 0; nt < 4; nt++) {
                int row0 = wm * 32 + mt * 16 + r;
                int col0 = wn * 32 + nt * 8 + 2 * cc;
                int qi0 = qBase + row0, qi1 = qi0 + 8;
                int kj0 = kBase + col0, kj1 = kj0 + 1;
                Ps[row0 * 68 + col0]       = (kj0 <= qi0) ? sacc[mt][nt][0] * scale : -1e30f;
                Ps[row0 * 68 + col0 + 1]   = (kj1 <= qi0) ? sacc[mt][nt][1] * scale : -1e30f;
                Ps[(row0 + 8) * 68 + col0]     = (kj0 <= qi1) ? sacc[mt][nt][2] * scale : -1e30f;
                Ps[(row0 + 8) * 68 + col0 + 1] = (kj1 <= qi1) ? sacc[mt][nt][3] * scale : -1e30f;
            }
        }
        __syncthreads();

        // load V tile transposed (V^T: [128 dims][64 pos], stride 68) — K no longer needed
#pragma unroll
        for (int i = 0; i < 16; i++) {
            int idx = tid + i * 128;
            int s = idx & 63, c4 = idx >> 6;   // c4: 0..31
            float4 v = *(const float4*)&cacheV[((size_t)g * S + kBase + s) * HEAD_DIM + c4 * 4];
            KVs[(c4 * 4 + 0) * 68 + s] = tf32r(v.x);
            KVs[(c4 * 4 + 1) * 68 + s] = tf32r(v.y);
            KVs[(c4 * 4 + 2) * 68 + s] = tf32r(v.z);
            KVs[(c4 * 4 + 3) * 68 + s] = tf32r(v.w);
        }

        // online softmax: 2 threads per row, 32 cols each
        {
            int row = tid >> 1;
            int half = tid & 1;
            float* prow = &Ps[row * 68 + half * 32];
            float mloc = -INFINITY;
#pragma unroll 8
            for (int j = 0; j < 32; j++) mloc = fmaxf(mloc, prow[j]);
            mloc = fmaxf(mloc, __shfl_xor_sync(0xffffffffu, mloc, 1));
            float mprev = mS[row];
            float mnew = fmaxf(mprev, mloc);
            float lsum = 0.0f;
#pragma unroll 8
            for (int j = 0; j < 32; j++) {
                float p = __expf(prow[j] - mnew);
                lsum += p;
                prow[j] = tf32r(p);
            }
            lsum += __shfl_xor_sync(0xffffffffu, lsum, 1);
            if (half == 0) {
                float corr = __expf(mprev - mnew);
                corrS[row] = corr;
                lS[row] = lS[row] * corr + lsum;
                mS[row] = mnew;
            }
        }
        __syncthreads();

        // rescale O accumulators by corr
#pragma unroll
        for (int mt = 0; mt < 2; mt++) {
            int row0 = wm * 32 + mt * 16 + r;
            float cr0 = corrS[row0];
            float cr1 = corrS[row0 + 8];
#pragma unroll
            for (int nt = 0; nt < 8; nt++) {
                oacc[mt][nt][0] *= cr0; oacc[mt][nt][1] *= cr0;
                oacc[mt][nt][2] *= cr1; oacc[mt][nt][3] *= cr1;
            }
        }

        // O += P @ V  (64x128x64)
#pragma unroll
        for (int ks = 0; ks < 8; ks++) {
            unsigned af[2][4];
#pragma unroll
            for (int mt = 0; mt < 2; mt++) {
                int m0 = wm * 32 + mt * 16;
                af[mt][0] = __float_as_uint(Ps[(m0 + r) * 68 + ks * 8 + cc]);
                af[mt][1] = __float_as_uint(Ps[(m0 + r + 8) * 68 + ks * 8 + cc]);
                af[mt][2] = __float_as_uint(Ps[(m0 + r) * 68 + ks * 8 + cc + 4]);
                af[mt][3] = __float_as_uint(Ps[(m0 + r + 8) * 68 + ks * 8 + cc + 4]);
            }
#pragma unroll
            for (int nt = 0; nt < 8; nt++) {
                int n0 = wn * 64 + nt * 8 + r;
                unsigned bf[2];
                bf[0] = __float_as_uint(KVs[n0 * 68 + ks * 8 + cc]);
                bf[1] = __float_as_uint(KVs[n0 * 68 + ks * 8 + cc + 4]);
#pragma unroll
                for (int mt = 0; mt < 2; mt++)
                    mma_tf32(oacc[mt][nt], af[mt], bf);
            }
        }
        __syncthreads();
    }

    // epilogue: normalize and write
#pragma unroll
    for (int mt = 0; mt < 2; mt++) {
        int row0 = wm * 32 + mt * 16 + r;
        float li0 = 1.0f / lS[row0];
        float li1 = 1.0f / lS[row0 + 8];
#pragma unroll
        for (int nt = 0; nt < 8; nt++) {
            int col = wn * 64 + nt * 8 + 2 * cc;
            float2 v0 = make_float2(oacc[mt][nt][0] * li0, oacc[mt][nt][1] * li0);
            float2 v1 = make_float2(oacc[mt][nt][2] * li1, oacc[mt][nt][3] * li1);
            *(float2*)&g_O[(size_t)(qBase + row0) * QDIM + h * HEAD_DIM + col] = v0;
            *(float2*)&g_O[(size_t)(qBase + row0 + 8) * QDIM + h * HEAD_DIM + col] = v1;
        }
    }
}

// ----------------------------------------------------------------------------
extern "C" void kernel_launch(void* const* d_in, const int* in_sizes, int n_in,
                              void* d_out, int out_size) {
    const float* x  = (const float*)d_in[0];
    const float* Wq = (const float*)d_in[1];
    const float* Wk = (const float*)d_in[2];
    const float* Wv = (const float*)d_in[3];
    const float* Wo = (const float*)d_in[4];
    const float* qw = (const float*)d_in[5];
    const float* kw = (const float*)d_in[6];

    float* out    = (float*)d_out;
    float* cacheK = out + (size_t)S * D_MODEL;
    float* cacheV = cacheK + (size_t)NUM_KV_HEADS * S * HEAD_DIM;

    float* dQ; cudaGetSymbolAddress((void**)&dQ, g_Q);
    float* dK; cudaGetSymbolAddress((void**)&dK, g_K);
    float* dV; cudaGetSymbolAddress((void**)&dV, g_V);
    float* dO; cudaGetSymbolAddress((void**)&dO, g_O);

    // 1) QKV projections (tf32 tensor cores)
    gemm_tf32<<<dim3(QDIM / GBN, S / GBM), 256>>>(x, Wq, dQ, S, QDIM, D_MODEL);
    gemm_tf32<<<dim3(KVDIM / GBN, S / GBM), 256>>>(x, Wk, dK, S, KVDIM, D_MODEL);
    gemm_tf32<<<dim3(KVDIM / GBN, S / GBM), 256>>>(x, Wv, dV, S, KVDIM, D_MODEL);

    // 2) RMSNorm + RoPE (Q in-place; K -> cache), V -> cache
    norm_rope_kernel<<<dim3(S, NUM_HEADS), HEAD_DIM>>>(dQ, dQ, qw, NUM_HEADS, 0);
    norm_rope_kernel<<<dim3(S, NUM_KV_HEADS), HEAD_DIM>>>(dK, cacheK, kw, NUM_KV_HEADS, 1);
    v_to_cache_kernel<<<dim3(S, NUM_KV_HEADS), HEAD_DIM>>>(dV, cacheV);

    // 3) Flash attention (tf32 mma)
    {
        size_t smem_bytes = FSMEM_FLOATS * sizeof(float); // 86784
        cudaFuncSetAttribute(flash_tf32, cudaFuncAttributeMaxDynamicSharedMemorySize,
                             (int)smem_bytes);
        flash_tf32<<<dim3(S / FQT, NUM_HEADS), 128, smem_bytes>>>(cacheK, cacheV);
    }

    // 4) Output projection
    gemm_tf32<<<dim3(D_MODEL / GBN, S / GBM), 256>>>(dO, Wo, out, S, D_MODEL, QDIM);
}